// round 2
// baseline (speedup 1.0000x reference)
#include <cuda_runtime.h>

#define D 384
#define N_ETYPES 8
#define VECS_PER_ROW (D / 4)               // 96 float4
#define VECS_PER_LANE (VECS_PER_ROW / 32)  // 3

__global__ void distmult_kernel(const float* __restrict__ h,
                                const int* __restrict__ u,
                                const int* __restrict__ v,
                                const int* __restrict__ etype,
                                const float* __restrict__ rel,
                                float* __restrict__ out,
                                int n_edges) {
    __shared__ float s_rel[N_ETYPES * D];   // 12 KB

    // Stage the tiny relation-weight table into shared memory (coalesced).
    for (int i = threadIdx.x; i < N_ETYPES * D; i += blockDim.x)
        s_rel[i] = rel[i];
    __syncthreads();

    int gwarp = (int)((blockIdx.x * (unsigned)blockDim.x + threadIdx.x) >> 5);
    int lane  = threadIdx.x & 31;
    if (gwarp >= n_edges) return;

    int ui = u[gwarp];
    int vi = v[gwarp];
    int ei = etype[gwarp];

    const float4* __restrict__ hu = (const float4*)(h + (size_t)ui * D);
    const float4* __restrict__ hv = (const float4*)(h + (size_t)vi * D);
    const float4* __restrict__ rr = (const float4*)(s_rel + ei * D);

    float acc = 0.0f;
    #pragma unroll
    for (int k = 0; k < VECS_PER_LANE; k++) {
        int idx = lane + k * 32;
        float4 a = hu[idx];
        float4 b = hv[idx];
        float4 c = rr[idx];
        acc = fmaf(a.x * c.x, b.x, acc);
        acc = fmaf(a.y * c.y, b.y, acc);
        acc = fmaf(a.z * c.z, b.z, acc);
        acc = fmaf(a.w * c.w, b.w, acc);
    }

    // Warp reduction
    #pragma unroll
    for (int o = 16; o > 0; o >>= 1)
        acc += __shfl_xor_sync(0xffffffffu, acc, o);

    if (lane == 0)
        out[gwarp] = 1.0f / (1.0f + __expf(-acc));
}

extern "C" void kernel_launch(void* const* d_in, const int* in_sizes, int n_in,
                              void* d_out, int out_size) {
    const float* h   = (const float*)d_in[0];
    const int*   u   = (const int*)d_in[1];
    const int*   v   = (const int*)d_in[2];
    const int*   et  = (const int*)d_in[3];
    const float* rel = (const float*)d_in[4];
    float*       out = (float*)d_out;

    int n_edges = in_sizes[1];                 // 250000
    const int threads = 256;                   // 8 warps = 8 edges per block
    int blocks = (n_edges + (threads / 32) - 1) / (threads / 32);
    distmult_kernel<<<blocks, threads>>>(h, u, v, et, rel, out, n_edges);
}

// round 3
// speedup vs baseline: 1.2003x; 1.2003x over previous
#include <cuda_runtime.h>

#define D 384
#define N_ETYPES 8
#define VECS_PER_ROW (D / 4)      // 96 float4 per row
#define LANES_PER_EDGE 16
#define VECS_PER_LANE (VECS_PER_ROW / LANES_PER_EDGE)  // 6
#define EDGES_PER_WARP 2

__global__ __launch_bounds__(256)
void distmult_kernel(const float* __restrict__ h,
                     const int* __restrict__ u,
                     const int* __restrict__ v,
                     const int* __restrict__ etype,
                     const float* __restrict__ rel,
                     float* __restrict__ out,
                     int n_edges) {
    __shared__ float s_rel[N_ETYPES * D];   // 12 KB

    for (int i = threadIdx.x; i < N_ETYPES * D; i += blockDim.x)
        s_rel[i] = rel[i];
    __syncthreads();

    unsigned gwarp = (blockIdx.x * blockDim.x + threadIdx.x) >> 5;
    int lane    = threadIdx.x & 31;
    int sub     = lane & (LANES_PER_EDGE - 1);   // 0..15
    int half    = lane >> 4;                     // which edge within the warp
    int edge    = (int)(gwarp * EDGES_PER_WARP + half);

    bool active = edge < n_edges;
    // Clamp so inactive lanes still execute loads safely (uniform control flow
    // keeps the load batch intact for the active half-warp).
    int e = active ? edge : 0;

    int ui = u[e];
    int vi = v[e];
    int ei = etype[e];

    const float4* __restrict__ hu = (const float4*)(h + (size_t)ui * D);
    const float4* __restrict__ hv = (const float4*)(h + (size_t)vi * D);
    const float4* __restrict__ rr = (const float4*)(s_rel + ei * D);

    // Front-batch all 12 global loads (6 per row) to maximize in-flight MLP.
    float4 a[VECS_PER_LANE], b[VECS_PER_LANE];
    #pragma unroll
    for (int k = 0; k < VECS_PER_LANE; k++) {
        int idx = sub + k * LANES_PER_EDGE;
        a[k] = hu[idx];
        b[k] = hv[idx];
    }

    float acc = 0.0f;
    #pragma unroll
    for (int k = 0; k < VECS_PER_LANE; k++) {
        int idx = sub + k * LANES_PER_EDGE;
        float4 c = rr[idx];
        acc = fmaf(a[k].x * c.x, b[k].x, acc);
        acc = fmaf(a[k].y * c.y, b[k].y, acc);
        acc = fmaf(a[k].z * c.z, b[k].z, acc);
        acc = fmaf(a[k].w * c.w, b[k].w, acc);
    }

    // Reduce within each 16-lane group (xor offsets stay inside the group).
    #pragma unroll
    for (int o = 8; o > 0; o >>= 1)
        acc += __shfl_xor_sync(0xffffffffu, acc, o);

    if (sub == 0 && active)
        out[edge] = 1.0f / (1.0f + __expf(-acc));
}

extern "C" void kernel_launch(void* const* d_in, const int* in_sizes, int n_in,
                              void* d_out, int out_size) {
    const float* h   = (const float*)d_in[0];
    const int*   u   = (const int*)d_in[1];
    const int*   v   = (const int*)d_in[2];
    const int*   et  = (const int*)d_in[3];
    const float* rel = (const float*)d_in[4];
    float*       out = (float*)d_out;

    int n_edges = in_sizes[1];                    // 250000
    const int threads = 256;                      // 8 warps = 16 edges per block
    int edges_per_block = (threads / 32) * EDGES_PER_WARP;
    int blocks = (n_edges + edges_per_block - 1) / edges_per_block;
    distmult_kernel<<<blocks, threads>>>(h, u, v, et, rel, out, n_edges);
}

// round 4
// speedup vs baseline: 1.4355x; 1.1959x over previous
#include <cuda_runtime.h>

#define D 384
#define N_ETYPES 8
#define ROW_F4 (D / 4)          // 96 float4 per row
#define SLOT_F4 (2 * ROW_F4)    // u row + v row = 192 float4 = 3072 B
#define DEPTH 3                 // pipeline stages per warp
#define WARPS 4
#define THREADS (WARPS * 32)
#define GRID 608                // ~4 blocks/SM on 148-152 SMs

__device__ __forceinline__ void cpa16(void* smem_dst, const void* gmem_src) {
    unsigned s = (unsigned)__cvta_generic_to_shared(smem_dst);
    asm volatile("cp.async.cg.shared.global [%0], [%1], 16;\n"
                 :: "r"(s), "l"(gmem_src) : "memory");
}
__device__ __forceinline__ void cpa_commit() {
    asm volatile("cp.async.commit_group;\n" ::: "memory");
}
__device__ __forceinline__ void cpa_wait() {
    asm volatile("cp.async.wait_group %0;\n" :: "n"(DEPTH - 1) : "memory");
}

__global__ __launch_bounds__(THREADS)
void distmult_kernel(const float* __restrict__ h,
                     const int* __restrict__ u,
                     const int* __restrict__ v,
                     const int* __restrict__ etype,
                     const float* __restrict__ rel,
                     float* __restrict__ out,
                     int n_edges) {
    __shared__ float4 buf[WARPS][DEPTH][SLOT_F4];   // 36864 B
    __shared__ float  s_rel[N_ETYPES * D];          // 12288 B  (total 48 KB)

    for (int i = threadIdx.x; i < N_ETYPES * D; i += THREADS)
        s_rel[i] = rel[i];
    __syncthreads();

    int wid  = threadIdx.x >> 5;
    int lane = threadIdx.x & 31;

    // Contiguous edge chunk per warp (keeps index loads L1-hot).
    int total_warps = GRID * WARPS;
    int gw   = blockIdx.x * WARPS + wid;
    int K    = (n_edges + total_warps - 1) / total_warps;
    int base = gw * K;
    int end  = base + K; if (end > n_edges) end = n_edges;

    const float4* rel4 = (const float4*)s_rel;

    // ── Prologue: fill DEPTH stages ──
    #pragma unroll
    for (int s = 0; s < DEPTH; s++) {
        int e = base + s;
        if (e < end) {
            int ui = __ldg(u + e);
            int vi = __ldg(v + e);
            const float4* hu = (const float4*)(h + (size_t)ui * D);
            const float4* hv = (const float4*)(h + (size_t)vi * D);
            #pragma unroll
            for (int k = 0; k < 3; k++) {
                cpa16(&buf[wid][s][lane + 32 * k],           hu + lane + 32 * k);
                cpa16(&buf[wid][s][ROW_F4 + lane + 32 * k],  hv + lane + 32 * k);
            }
        }
        cpa_commit();
    }

    // ── Steady state ──
    int s = 0;
    for (int e = base; e < end; e++) {
        cpa_wait();   // oldest group (this lane's own bytes) complete

        const float4* slot = buf[wid][s];
        int ei = __ldg(etype + e);
        const float4* rr = rel4 + ei * ROW_F4;

        float acc = 0.0f;
        #pragma unroll
        for (int k = 0; k < 3; k++) {
            int idx  = lane + 32 * k;
            float4 a = slot[idx];
            float4 b = slot[ROW_F4 + idx];
            float4 c = rr[idx];
            acc = fmaf(a.x * c.x, b.x, acc);
            acc = fmaf(a.y * c.y, b.y, acc);
            acc = fmaf(a.z * c.z, b.z, acc);
            acc = fmaf(a.w * c.w, b.w, acc);
        }
        #pragma unroll
        for (int o = 16; o > 0; o >>= 1)
            acc += __shfl_xor_sync(0xffffffffu, acc, o);
        if (lane == 0)
            out[e] = 1.0f / (1.0f + __expf(-acc));

        // Refill the slot we just consumed with edge e+DEPTH.
        // (Safe without a barrier: the async smem write lands >=200cyc after
        //  issue, far after the 29cyc LDS reads above; per-lane data only.)
        int ne = e + DEPTH;
        if (ne < end) {
            int ui = __ldg(u + ne);
            int vi = __ldg(v + ne);
            const float4* hu = (const float4*)(h + (size_t)ui * D);
            const float4* hv = (const float4*)(h + (size_t)vi * D);
            #pragma unroll
            for (int k = 0; k < 3; k++) {
                cpa16(&buf[wid][s][lane + 32 * k],          hu + lane + 32 * k);
                cpa16(&buf[wid][s][ROW_F4 + lane + 32 * k], hv + lane + 32 * k);
            }
        }
        cpa_commit();

        s = (s + 1 == DEPTH) ? 0 : s + 1;
    }
}

extern "C" void kernel_launch(void* const* d_in, const int* in_sizes, int n_in,
                              void* d_out, int out_size) {
    const float* h   = (const float*)d_in[0];
    const int*   u   = (const int*)d_in[1];
    const int*   v   = (const int*)d_in[2];
    const int*   et  = (const int*)d_in[3];
    const float* rel = (const float*)d_in[4];
    float*       out = (float*)d_out;

    int n_edges = in_sizes[1];   // 250000
    distmult_kernel<<<GRID, THREADS>>>(h, u, v, et, rel, out, n_edges);
}

// round 6
// speedup vs baseline: 1.4593x; 1.0166x over previous
#include <cuda_runtime.h>

#define D 384
#define N_ETYPES 8
#define ROW_F4 (D / 4)          // 96 float4 per row
#define SLOT_F4 (2 * ROW_F4)    // u row + v row = 3072 B
#define DEPTH 2                 // pipeline stages per warp
#define WARPS 16
#define THREADS (WARPS * 32)
#define BLOCKS 304              // 2 blocks/SM x 152 SMs

#define SMEM_BYTES (WARPS * DEPTH * SLOT_F4 * 16 + N_ETYPES * D * 4)  // 110592

__device__ __forceinline__ void cpa16(void* smem_dst, const void* gmem_src) {
    unsigned s = (unsigned)__cvta_generic_to_shared(smem_dst);
    asm volatile("cp.async.cg.shared.global [%0], [%1], 16;\n"
                 :: "r"(s), "l"(gmem_src) : "memory");
}
__device__ __forceinline__ void cpa_commit() {
    asm volatile("cp.async.commit_group;\n" ::: "memory");
}
__device__ __forceinline__ void cpa_wait() {
    asm volatile("cp.async.wait_group %0;\n" :: "n"(DEPTH - 1) : "memory");
}

__global__ __launch_bounds__(THREADS, 2)
void distmult_kernel(const float* __restrict__ h,
                     const int* __restrict__ u,
                     const int* __restrict__ v,
                     const int* __restrict__ etype,
                     const float* __restrict__ rel,
                     float* __restrict__ out,
                     int n_edges) {
    extern __shared__ char smem[];
    float4* buf   = (float4*)smem;                              // [WARPS][DEPTH][SLOT_F4]
    float*  s_rel = (float*)(smem + WARPS * DEPTH * SLOT_F4 * 16);

    for (int i = threadIdx.x; i < N_ETYPES * D; i += THREADS)
        s_rel[i] = rel[i];
    __syncthreads();

    int wid  = threadIdx.x >> 5;
    int lane = threadIdx.x & 31;
    float4* wbuf = buf + wid * (DEPTH * SLOT_F4);

    // Contiguous edge chunk per warp (keeps index loads L1-hot).
    int total_warps = BLOCKS * WARPS;
    int gw   = blockIdx.x * WARPS + wid;
    int K    = (n_edges + total_warps - 1) / total_warps;
    int base = gw * K;
    int end  = base + K; if (end > n_edges) end = n_edges;

    const float4* rel4 = (const float4*)s_rel;

    // ── Prologue: fill DEPTH stages ──
    #pragma unroll
    for (int s = 0; s < DEPTH; s++) {
        int e = base + s;
        if (e < end) {
            int ui = __ldg(u + e);
            int vi = __ldg(v + e);
            const float4* hu = (const float4*)(h + (size_t)ui * D);
            const float4* hv = (const float4*)(h + (size_t)vi * D);
            float4* slot = wbuf + s * SLOT_F4;
            #pragma unroll
            for (int k = 0; k < 3; k++) {
                cpa16(slot + lane + 32 * k,          hu + lane + 32 * k);
                cpa16(slot + ROW_F4 + lane + 32 * k, hv + lane + 32 * k);
            }
        }
        cpa_commit();
    }

    // ── Steady state ──
    int s = 0;
    for (int e = base; e < end; e++) {
        cpa_wait();   // this lane's own bytes for edge e are complete

        const float4* slot = wbuf + s * SLOT_F4;
        int ei = __ldg(etype + e);
        const float4* rr = rel4 + ei * ROW_F4;

        float acc0 = 0.0f, acc1 = 0.0f;
        #pragma unroll
        for (int k = 0; k < 3; k++) {
            int idx  = lane + 32 * k;
            float4 a = slot[idx];
            float4 b = slot[ROW_F4 + idx];
            float4 c = rr[idx];
            acc0 = fmaf(a.x * c.x, b.x, acc0);
            acc1 = fmaf(a.y * c.y, b.y, acc1);
            acc0 = fmaf(a.z * c.z, b.z, acc0);
            acc1 = fmaf(a.w * c.w, b.w, acc1);
        }

        float acc = acc0 + acc1;
        #pragma unroll
        for (int o = 16; o > 0; o >>= 1)
            acc += __shfl_xor_sync(0xffffffffu, acc, o);
        if (lane == 0)
            out[e] = 1.0f / (1.0f + __expf(-acc));

        // Refill the slot just consumed with edge e+DEPTH (per-lane bytes only;
        // async write lands hundreds of cycles after the LDS reads above).
        int ne = e + DEPTH;
        if (ne < end) {
            int ui = __ldg(u + ne);
            int vi = __ldg(v + ne);
            const float4* hu = (const float4*)(h + (size_t)ui * D);
            const float4* hv = (const float4*)(h + (size_t)vi * D);
            float4* wslot = wbuf + s * SLOT_F4;
            #pragma unroll
            for (int k = 0; k < 3; k++) {
                cpa16(wslot + lane + 32 * k,          hu + lane + 32 * k);
                cpa16(wslot + ROW_F4 + lane + 32 * k, hv + lane + 32 * k);
            }
        }
        cpa_commit();

        s ^= 1;   // DEPTH == 2
    }
}

extern "C" void kernel_launch(void* const* d_in, const int* in_sizes, int n_in,
                              void* d_out, int out_size) {
    const float* h   = (const float*)d_in[0];
    const int*   u   = (const int*)d_in[1];
    const int*   v   = (const int*)d_in[2];
    const int*   et  = (const int*)d_in[3];
    const float* rel = (const float*)d_in[4];
    float*       out = (float*)d_out;

    int n_edges = in_sizes[1];   // 250000

    cudaFuncSetAttribute(distmult_kernel,
                         cudaFuncAttributeMaxDynamicSharedMemorySize, SMEM_BYTES);
    distmult_kernel<<<BLOCKS, THREADS, SMEM_BYTES>>>(h, u, v, et, rel, out, n_edges);
}